// round 3
// baseline (speedup 1.0000x reference)
#include <cuda_runtime.h>
#include <math.h>

// Problem constants (fixed shapes per reference)
#define NN    50000
#define EMBD  256
#define HD    128
#define EB    100000
#define ETOT  (2*EB + NN)      // 250000 directed edges incl self-loops
#define KQVW  768

// ------------- persistent device scratch (allocation-free rule) -------------
__device__ float    g_kqv[(size_t)NN * KQVW];   // [N, 768]  q|k|v
__device__ float    g_pk [(size_t)NN * EMBD];   // [N, H, 128]  (k/sqrt)@W1_top
__device__ float    g_pq [(size_t)NN * EMBD];   // [N, H, 128]  q@W1_bot + b1
__device__ float    g_agg[(size_t)NN * EMBD];   // [N, 256] sum alpha*v
__device__ float    g_a  [(size_t)ETOT * 2];    // per-edge logits then exp
__device__ unsigned g_m  [NN * 2];              // encoded segment max
__device__ float    g_s  [NN * 2];              // segment sum of exp
__device__ float    g_deg[NN];                  // in-degree (for bout term)

// monotone encoding of float for atomicMax on unsigned
__device__ __forceinline__ unsigned fenc(float f) {
    unsigned u = __float_as_uint(f);
    return (u & 0x80000000u) ? ~u : (u | 0x80000000u);
}
__device__ __forceinline__ float fdec(unsigned u) {
    return __uint_as_float((u & 0x80000000u) ? (u & 0x7fffffffu) : ~u);
}

// decode edge e of the concatenated [fwd | reverse | self-loop] edge list
// edge_index arrives as int32 (JAX default x64-disabled), shape [2, EB]
__device__ __forceinline__ void edge_sd(int e, const int* __restrict__ ei,
                                        int& s, int& d) {
    if (e < EB)          { s = ei[e];          d = ei[EB + e]; }
    else if (e < 2 * EB) { int t = e - EB; s = ei[EB + t]; d = ei[t]; }
    else                 { int t = e - 2 * EB; s = t; d = t; }
}

// ----------------------------- init ---------------------------------------
__global__ void init_kernel() {
    int i = blockIdx.x * blockDim.x + threadIdx.x;
    if (i < NN * EMBD) g_agg[i] = 0.f;
    if (i < NN * 2)   { g_m[i] = 0u; g_s[i] = 0.f; }
    if (i < NN)         g_deg[i] = 0.f;
}

// ----------------------------- SGEMM ---------------------------------------
// C[M,N] = scaleA * A[M,K] @ B[K,N]  (+ bias per col)
// EPI==1: v = acc + deg[row]*bias[col]; v = relu(v) + x[row,col]
// Requires: N multiple of 128, K multiple of 16, 16B-aligned pointers.
template<int EPI>
__global__ void __launch_bounds__(256, 2)
sgemm(const float* __restrict__ A, int lda,
      const float* __restrict__ B, int ldb,
      float* __restrict__ C, int ldc,
      const float* __restrict__ bias,
      const float* __restrict__ x,
      int M, int K, float scaleA)
{
    __shared__ float As[16][128];
    __shared__ float Bs[16][128];
    const int tid = threadIdx.x;
    const int bm0 = blockIdx.y * 128;
    const int bn0 = blockIdx.x * 128;
    const int tx = tid & 15, ty = tid >> 4;

    float acc[8][8];
    #pragma unroll
    for (int i = 0; i < 8; i++)
        #pragma unroll
        for (int j = 0; j < 8; j++) acc[i][j] = 0.f;

    const int rowA = tid >> 2;          // 0..63
    const int colA = (tid & 3) * 4;     // 0,4,8,12
    const int kB   = tid >> 5;          // 0..7
    const int colB = (tid & 31) * 4;    // 0..124

    for (int k0 = 0; k0 < K; k0 += 16) {
        #pragma unroll
        for (int i = 0; i < 2; i++) {
            int r  = rowA + i * 64;
            int rg = bm0 + r;
            float4 v = make_float4(0.f, 0.f, 0.f, 0.f);
            if (rg < M) v = *(const float4*)(A + (size_t)rg * lda + k0 + colA);
            As[colA + 0][r] = v.x * scaleA;
            As[colA + 1][r] = v.y * scaleA;
            As[colA + 2][r] = v.z * scaleA;
            As[colA + 3][r] = v.w * scaleA;
        }
        #pragma unroll
        for (int i = 0; i < 2; i++) {
            int kk = kB + i * 8;
            *(float4*)(&Bs[kk][colB]) =
                *(const float4*)(B + (size_t)(k0 + kk) * ldb + bn0 + colB);
        }
        __syncthreads();
        #pragma unroll
        for (int kk = 0; kk < 16; kk++) {
            float af[8], bf[8];
            *(float4*)(af)     = *(const float4*)(&As[kk][ty * 8]);
            *(float4*)(af + 4) = *(const float4*)(&As[kk][ty * 8 + 4]);
            *(float4*)(bf)     = *(const float4*)(&Bs[kk][tx * 8]);
            *(float4*)(bf + 4) = *(const float4*)(&Bs[kk][tx * 8 + 4]);
            #pragma unroll
            for (int i = 0; i < 8; i++)
                #pragma unroll
                for (int j = 0; j < 8; j++)
                    acc[i][j] = fmaf(af[i], bf[j], acc[i][j]);
        }
        __syncthreads();
    }

    #pragma unroll
    for (int i = 0; i < 8; i++) {
        int rg = bm0 + ty * 8 + i;
        if (rg >= M) continue;
        #pragma unroll
        for (int j = 0; j < 8; j++) {
            int cg = bn0 + tx * 8 + j;
            float v = acc[i][j];
            if (EPI == 0) {
                if (bias) v += bias[cg];
                C[(size_t)rg * ldc + cg] = v;
            } else {
                v += g_deg[rg] * bias[cg];
                v = fmaxf(v, 0.f) + x[(size_t)rg * EMBD + cg];
                C[(size_t)rg * ldc + cg] = v;
            }
        }
    }
}

// --------------------- edge logits + segment max ----------------------------
// one warp per edge; a[e,h] = relu(Pk[src,h]+Pq[dst,h]) . W2 + b2
__global__ void edge_logits(const int* __restrict__ ei,
                            const float* __restrict__ W2,
                            const float* __restrict__ b2)
{
    int e    = (blockIdx.x * blockDim.x + threadIdx.x) >> 5;
    int lane = threadIdx.x & 31;
    if (e >= ETOT) return;
    int s, d; edge_sd(e, ei, s, d);
    const float4* pk = (const float4*)(g_pk + (size_t)s * EMBD);
    const float4* pq = (const float4*)(g_pq + (size_t)d * EMBD);
    const float4  wv = ((const float4*)W2)[lane];

    float4 ka = pk[lane],      qa = pq[lane];
    float p0 = fmaxf(ka.x + qa.x, 0.f) * wv.x + fmaxf(ka.y + qa.y, 0.f) * wv.y
             + fmaxf(ka.z + qa.z, 0.f) * wv.z + fmaxf(ka.w + qa.w, 0.f) * wv.w;
    float4 kb = pk[32 + lane], qb = pq[32 + lane];
    float p1 = fmaxf(kb.x + qb.x, 0.f) * wv.x + fmaxf(kb.y + qb.y, 0.f) * wv.y
             + fmaxf(kb.z + qb.z, 0.f) * wv.z + fmaxf(kb.w + qb.w, 0.f) * wv.w;

    #pragma unroll
    for (int o = 16; o > 0; o >>= 1) {
        p0 += __shfl_xor_sync(0xffffffffu, p0, o);
        p1 += __shfl_xor_sync(0xffffffffu, p1, o);
    }
    if (lane == 0) {
        float bb = b2[0];
        float a0 = p0 + bb, a1 = p1 + bb;
        g_a[(size_t)e * 2 + 0] = a0;
        g_a[(size_t)e * 2 + 1] = a1;
        atomicMax(&g_m[d * 2 + 0], fenc(a0));
        atomicMax(&g_m[d * 2 + 1], fenc(a1));
    }
}

// --------------------- exp + segment sum ------------------------------------
__global__ void edge_exp(const int* __restrict__ ei) {
    int t = blockIdx.x * blockDim.x + threadIdx.x;
    if (t >= ETOT * 2) return;
    int e = t >> 1, h = t & 1;
    int s, d; edge_sd(e, ei, s, d);
    float ex = expf(g_a[t] - fdec(g_m[d * 2 + h]));
    g_a[t] = ex;
    atomicAdd(&g_s[d * 2 + h], ex);
    if (h == 0) atomicAdd(&g_deg[d], 1.0f);
}

// --------------------- weighted scatter of v --------------------------------
__global__ void edge_agg(const int* __restrict__ ei) {
    __shared__ float sh_alpha[2];
    __shared__ int sh_s, sh_d;
    int e = blockIdx.x;
    int c = threadIdx.x;  // 0..255
    if (c == 0) {
        int s, d; edge_sd(e, ei, s, d);
        sh_s = s; sh_d = d;
    }
    __syncthreads();
    int s = sh_s, d = sh_d;
    if (c < 2) sh_alpha[c] = g_a[(size_t)e * 2 + c] / (g_s[d * 2 + c] + 1e-16f);
    __syncthreads();
    int h = c >> 7;
    float val = sh_alpha[h] * g_kqv[(size_t)s * KQVW + 512 + c];
    atomicAdd(&g_agg[(size_t)d * EMBD + c], val);
}

// ----------------------------- launch ---------------------------------------
extern "C" void kernel_launch(void* const* d_in, const int* in_sizes, int n_in,
                              void* d_out, int out_size)
{
    const float* x    = (const float*)d_in[0];
    const int*   ei   = (const int*)d_in[1];
    const float* Wkqv = (const float*)d_in[2];
    const float* bkqv = (const float*)d_in[3];
    const float* W1   = (const float*)d_in[4];
    const float* b1   = (const float*)d_in[5];
    const float* W2   = (const float*)d_in[6];
    const float* b2   = (const float*)d_in[7];
    const float* Wout = (const float*)d_in[8];
    const float* bout = (const float*)d_in[9];
    float*       out  = (float*)d_out;

    float *kqv, *pk, *pq, *agg;
    cudaGetSymbolAddress((void**)&kqv, g_kqv);
    cudaGetSymbolAddress((void**)&pk,  g_pk);
    cudaGetSymbolAddress((void**)&pq,  g_pq);
    cudaGetSymbolAddress((void**)&agg, g_agg);

    const int M = NN;
    const float inv_sqrt_hd = 0.08838834764831845f;  // 1/sqrt(128)

    // init scratch (agg/m/s/deg)
    {
        int n = NN * EMBD;
        init_kernel<<<(n + 255) / 256, 256>>>();
    }

    dim3 blk(256);
    int mblocks = (M + 127) / 128;

    // kqv = x @ Wkqv + bkqv   [50000,768]
    sgemm<0><<<dim3(KQVW / 128, mblocks), blk>>>(
        x, EMBD, Wkqv, KQVW, kqv, KQVW, bkqv, nullptr, M, EMBD, 1.0f);

    // per head: Pk = (k/sqrt(hd)) @ W1[:128], Pq = q @ W1[128:] + b1
    for (int h = 0; h < 2; h++) {
        sgemm<0><<<dim3(1, mblocks), blk>>>(
            kqv + EMBD + h * HD, KQVW, W1, HD,
            pk + h * HD, EMBD, nullptr, nullptr, M, HD, inv_sqrt_hd);
        sgemm<0><<<dim3(1, mblocks), blk>>>(
            kqv + h * HD, KQVW, W1 + HD * HD, HD,
            pq + h * HD, EMBD, b1, nullptr, M, HD, 1.0f);
    }

    // edge logits + segment max
    edge_logits<<<(ETOT + 7) / 8, 256>>>(ei, W2, b2);

    // exp + segment sum (+degree)
    edge_exp<<<(ETOT * 2 + 255) / 256, 256>>>(ei);

    // scatter alpha * v into agg
    edge_agg<<<ETOT, 256>>>(ei);

    // out = relu(agg @ Wout + deg*bout) + x
    sgemm<1><<<dim3(EMBD / 128, mblocks), blk>>>(
        agg, EMBD, Wout, EMBD, out, EMBD, bout, x, M, EMBD, 1.0f);
}

// round 9
// speedup vs baseline: 1.3030x; 1.3030x over previous
#include <cuda_runtime.h>
#include <math.h>

#define NN    50000
#define EMBD  256
#define HD    128
#define EB    100000
#define ETOT  (2*EB + NN)      // 250000 directed edges incl self-loops
#define NCOMB 768              // v(256) | pk(256) | pq(256)

// ------------- persistent device scratch (allocation-free rule) -------------
__device__ __align__(16) float g_vpp [(size_t)NN * NCOMB];  // [N, 768] v|pk|pq
__device__ __align__(16) float g_wcf [EMBD * NCOMB];        // [k, n] fused weights
__device__ float               g_bcomb[NCOMB];              // fused bias
__device__ __align__(16) float g_agg [(size_t)NN * EMBD];   // sum alpha*v
__device__ float    g_a  [(size_t)ETOT * 2];                // logits then exp
__device__ unsigned g_m  [NN * 2];                          // encoded segment max
__device__ float    g_s  [NN * 2];                          // segment sum of exp
__device__ float    g_deg[NN];                              // in-degree

// monotone encoding of float for atomicMax on unsigned
__device__ __forceinline__ unsigned fenc(float f) {
    unsigned u = __float_as_uint(f);
    return (u & 0x80000000u) ? ~u : (u | 0x80000000u);
}
__device__ __forceinline__ float fdec(unsigned u) {
    return __uint_as_float((u & 0x80000000u) ? (u & 0x7fffffffu) : ~u);
}

// decode edge e of the concatenated [fwd | reverse | self-loop] edge list (int32)
__device__ __forceinline__ void edge_sd(int e, const int* __restrict__ ei,
                                        int& s, int& d) {
    if (e < EB)          { s = ei[e];              d = ei[EB + e]; }
    else if (e < 2 * EB) { int t = e - EB; s = ei[EB + t]; d = ei[t]; }
    else                 { int t = e - 2 * EB; s = t; d = t; }
}

// ----------------------------- init ---------------------------------------
__global__ void init_k() {
    int i = blockIdx.x * blockDim.x + threadIdx.x;
    if (i < NN * 64) ((float4*)g_agg)[i] = make_float4(0.f, 0.f, 0.f, 0.f);
    if (i < NN * 2) { g_m[i] = 0u; g_s[i] = 0.f; }
    if (i < NN) g_deg[i] = 0.f;
}

// -------- fold W1 through Wkqv: W_comb[k][n], n: 0..255 v | 256..511 pk | 512..767 pq
__global__ void prep_w(const float* __restrict__ Wkqv, const float* __restrict__ bkqv,
                       const float* __restrict__ W1,   const float* __restrict__ b1) {
    const float INVSQ = 0.08838834764831845f;   // 1/sqrt(128)
    int n = blockIdx.x;      // 0..767
    int k = threadIdx.x;     // 0..255
    float val, bval = 0.f;
    if (n < 256) {
        val  = Wkqv[(size_t)k * 768 + 512 + n];          // v block
        bval = bkqv[512 + n];
    } else if (n < 512) {                                 // pk = (k/sqrt)@W1_top
        int h = (n - 256) >> 7, j = (n - 256) & 127;
        int c0 = 256 + h * 128;                           // k columns of Wkqv
        float acc = 0.f;
        for (int m = 0; m < 128; m++)
            acc += Wkqv[(size_t)k * 768 + c0 + m] * W1[m * 128 + j];
        val = acc * INVSQ;
        if (k == 0) {
            float b = 0.f;
            for (int m = 0; m < 128; m++) b += bkqv[c0 + m] * W1[m * 128 + j];
            bval = b * INVSQ;
        }
    } else {                                              // pq = q@W1_bot + b1
        int h = (n - 512) >> 7, j = (n - 512) & 127;
        int c0 = h * 128;                                 // q columns of Wkqv
        float acc = 0.f;
        for (int m = 0; m < 128; m++)
            acc += Wkqv[(size_t)k * 768 + c0 + m] * W1[(128 + m) * 128 + j];
        val = acc;
        if (k == 0) {
            float b = b1[j];
            for (int m = 0; m < 128; m++) b += bkqv[c0 + m] * W1[(128 + m) * 128 + j];
            bval = b;
        }
    }
    g_wcf[(size_t)k * NCOMB + n] = val;
    if (k == 0) g_bcomb[n] = bval;
}

// ----------------------------- SGEMM (proven R2 kernel) ---------------------
// C[M,N] = A[M,K] @ B[K,N] (+ bias per col)
// EPI==1: v = acc + deg[row]*bias[col]; v = relu(v) + x[row,col]
template<int EPI>
__global__ void __launch_bounds__(256, 2)
sgemm(const float* __restrict__ A, int lda,
      const float* __restrict__ B, int ldb,
      float* __restrict__ C, int ldc,
      const float* __restrict__ bias,
      const float* __restrict__ x,
      int M, int K)
{
    __shared__ float As[16][128];
    __shared__ float Bs[16][128];
    const int tid = threadIdx.x;
    const int bm0 = blockIdx.y * 128;
    const int bn0 = blockIdx.x * 128;
    const int tx = tid & 15, ty = tid >> 4;

    float acc[8][8];
    #pragma unroll
    for (int i = 0; i < 8; i++)
        #pragma unroll
        for (int j = 0; j < 8; j++) acc[i][j] = 0.f;

    const int rowA = tid >> 2;          // 0..63
    const int colA = (tid & 3) * 4;     // 0,4,8,12
    const int kB   = tid >> 5;          // 0..7
    const int colB = (tid & 31) * 4;    // 0..124

    for (int k0 = 0; k0 < K; k0 += 16) {
        #pragma unroll
        for (int i = 0; i < 2; i++) {
            int r  = rowA + i * 64;
            int rg = bm0 + r;
            float4 v = make_float4(0.f, 0.f, 0.f, 0.f);
            if (rg < M) v = *(const float4*)(A + (size_t)rg * lda + k0 + colA);
            As[colA + 0][r] = v.x;
            As[colA + 1][r] = v.y;
            As[colA + 2][r] = v.z;
            As[colA + 3][r] = v.w;
        }
        #pragma unroll
        for (int i = 0; i < 2; i++) {
            int kk = kB + i * 8;
            *(float4*)(&Bs[kk][colB]) =
                *(const float4*)(B + (size_t)(k0 + kk) * ldb + bn0 + colB);
        }
        __syncthreads();
        #pragma unroll
        for (int kk = 0; kk < 16; kk++) {
            float af[8], bf[8];
            *(float4*)(af)     = *(const float4*)(&As[kk][ty * 8]);
            *(float4*)(af + 4) = *(const float4*)(&As[kk][ty * 8 + 4]);
            *(float4*)(bf)     = *(const float4*)(&Bs[kk][tx * 8]);
            *(float4*)(bf + 4) = *(const float4*)(&Bs[kk][tx * 8 + 4]);
            #pragma unroll
            for (int i = 0; i < 8; i++)
                #pragma unroll
                for (int j = 0; j < 8; j++)
                    acc[i][j] = fmaf(af[i], bf[j], acc[i][j]);
        }
        __syncthreads();
    }

    #pragma unroll
    for (int i = 0; i < 8; i++) {
        int rg = bm0 + ty * 8 + i;
        if (rg >= M) continue;
        #pragma unroll
        for (int j = 0; j < 8; j++) {
            int cg = bn0 + tx * 8 + j;
            float v = acc[i][j];
            if (EPI == 0) {
                v += bias[cg];
                C[(size_t)rg * ldc + cg] = v;
            } else {
                v += g_deg[rg] * bias[cg];
                v = fmaxf(v, 0.f) + x[(size_t)rg * EMBD + cg];
                C[(size_t)rg * ldc + cg] = v;
            }
        }
    }
}

// --------------------- edge logits + segment max ----------------------------
__global__ void edge_logits(const int* __restrict__ ei,
                            const float* __restrict__ W2,
                            const float* __restrict__ b2)
{
    int e    = (blockIdx.x * blockDim.x + threadIdx.x) >> 5;
    int lane = threadIdx.x & 31;
    if (e >= ETOT) return;
    int s, d; edge_sd(e, ei, s, d);
    const float4* pk = (const float4*)(g_vpp + (size_t)s * NCOMB + 256);
    const float4* pq = (const float4*)(g_vpp + (size_t)d * NCOMB + 512);
    const float4  wv = ((const float4*)W2)[lane];

    float4 ka = pk[lane],      qa = pq[lane];
    float p0 = fmaxf(ka.x + qa.x, 0.f) * wv.x + fmaxf(ka.y + qa.y, 0.f) * wv.y
             + fmaxf(ka.z + qa.z, 0.f) * wv.z + fmaxf(ka.w + qa.w, 0.f) * wv.w;
    float4 kb = pk[32 + lane], qb = pq[32 + lane];
    float p1 = fmaxf(kb.x + qb.x, 0.f) * wv.x + fmaxf(kb.y + qb.y, 0.f) * wv.y
             + fmaxf(kb.z + qb.z, 0.f) * wv.z + fmaxf(kb.w + qb.w, 0.f) * wv.w;

    #pragma unroll
    for (int o = 16; o > 0; o >>= 1) {
        p0 += __shfl_xor_sync(0xffffffffu, p0, o);
        p1 += __shfl_xor_sync(0xffffffffu, p1, o);
    }
    if (lane == 0) {
        float bb = b2[0];
        float a0 = p0 + bb, a1 = p1 + bb;
        g_a[(size_t)e * 2 + 0] = a0;
        g_a[(size_t)e * 2 + 1] = a1;
        atomicMax(&g_m[d * 2 + 0], fenc(a0));
        atomicMax(&g_m[d * 2 + 1], fenc(a1));
    }
}

// --------------------- exp + segment sum ------------------------------------
__global__ void edge_exp(const int* __restrict__ ei) {
    int t = blockIdx.x * blockDim.x + threadIdx.x;
    if (t >= ETOT * 2) return;
    int e = t >> 1, h = t & 1;
    int s, d; edge_sd(e, ei, s, d);
    float ex = expf(g_a[t] - fdec(g_m[d * 2 + h]));
    g_a[t] = ex;
    atomicAdd(&g_s[d * 2 + h], ex);
    if (h == 0) atomicAdd(&g_deg[d], 1.0f);
}

// --------------------- weighted scatter of v (warp per edge) ----------------
__global__ void edge_agg(const int* __restrict__ ei) {
    int e    = (blockIdx.x * blockDim.x + threadIdx.x) >> 5;
    int lane = threadIdx.x & 31;
    if (e >= ETOT) return;
    int s, d; edge_sd(e, ei, s, d);
    float al0 = g_a[(size_t)e * 2 + 0] / (g_s[d * 2 + 0] + 1e-16f);
    float al1 = g_a[(size_t)e * 2 + 1] / (g_s[d * 2 + 1] + 1e-16f);
    const float4* v = (const float4*)(g_vpp + (size_t)s * NCOMB);
    float4 v0 = v[lane], v1 = v[32 + lane];
    float* dst0 = g_agg + (size_t)d * EMBD + 4 * lane;
    atomicAdd(dst0 + 0, v0.x * al0);
    atomicAdd(dst0 + 1, v0.y * al0);
    atomicAdd(dst0 + 2, v0.z * al0);
    atomicAdd(dst0 + 3, v0.w * al0);
    float* dst1 = dst0 + 128;
    atomicAdd(dst1 + 0, v1.x * al1);
    atomicAdd(dst1 + 1, v1.y * al1);
    atomicAdd(dst1 + 2, v1.z * al1);
    atomicAdd(dst1 + 3, v1.w * al1);
}

// ----------------------------- launch ---------------------------------------
extern "C" void kernel_launch(void* const* d_in, const int* in_sizes, int n_in,
                              void* d_out, int out_size)
{
    const float* x    = (const float*)d_in[0];
    const int*   ei   = (const int*)d_in[1];
    const float* Wkqv = (const float*)d_in[2];
    const float* bkqv = (const float*)d_in[3];
    const float* W1   = (const float*)d_in[4];
    const float* b1   = (const float*)d_in[5];
    const float* W2   = (const float*)d_in[6];
    const float* b2   = (const float*)d_in[7];
    const float* Wout = (const float*)d_in[8];
    const float* bout = (const float*)d_in[9];
    float*       out  = (float*)d_out;

    float *vpp, *wcf, *bcomb, *agg;
    cudaGetSymbolAddress((void**)&vpp,   g_vpp);
    cudaGetSymbolAddress((void**)&wcf,   g_wcf);
    cudaGetSymbolAddress((void**)&bcomb, g_bcomb);
    cudaGetSymbolAddress((void**)&agg,   g_agg);

    const int mtiles = (NN + 127) / 128;   // 391
    dim3 blk(256);

    init_k<<<(NN * 64 + 255) / 256, 256>>>();
    prep_w<<<NCOMB, 256>>>(Wkqv, bkqv, W1, b1);

    // GEMM1: vpp[N,768] = x @ W_comb + b_comb   (v | pk | pq)
    sgemm<0><<<dim3(NCOMB / 128, mtiles), blk>>>(
        x, EMBD, wcf, NCOMB, vpp, NCOMB, bcomb, nullptr, NN, EMBD);

    // edge pipeline
    edge_logits<<<(ETOT + 7) / 8, 256>>>(ei, W2, b2);
    edge_exp<<<(ETOT * 2 + 255) / 256, 256>>>(ei);
    edge_agg<<<(ETOT + 7) / 8, 256>>>(ei);

    // GEMM2: out = relu(agg @ Wout + deg*bout) + x
    sgemm<1><<<dim3(EMBD / 128, mtiles), blk>>>(
        agg, EMBD, Wout, EMBD, out, EMBD, bout, x, NN, EMBD);
}

// round 10
// speedup vs baseline: 1.3573x; 1.0416x over previous
#include <cuda_runtime.h>
#include <math.h>
#include <cstdint>

#define NN    50000
#define EMBD  256
#define HD    128
#define EB    100000
#define ETOT  (2*EB + NN)      // 250000 directed edges incl self-loops
#define NCOMB 768              // v(256) | pk(256) | pq(256)

// ------------- persistent device scratch (allocation-free rule) -------------
__device__ __align__(16) float g_vpp [(size_t)NN * NCOMB];  // [N, 768] v|pk|pq
__device__ __align__(16) float g_wcf [EMBD * NCOMB];        // [k, n] fused weights
__device__ float               g_bcomb[NCOMB];              // fused bias
__device__ __align__(16) float g_agg [(size_t)NN * EMBD];   // sum alpha*v
__device__ float    g_a  [(size_t)ETOT * 2];                // logits then exp
__device__ unsigned g_m  [NN * 2];                          // encoded segment max
__device__ float    g_s  [NN * 2];                          // segment sum of exp
__device__ float    g_deg[NN];                              // in-degree

// monotone encoding of float for atomicMax on unsigned
__device__ __forceinline__ unsigned fenc(float f) {
    unsigned u = __float_as_uint(f);
    return (u & 0x80000000u) ? ~u : (u | 0x80000000u);
}
__device__ __forceinline__ float fdec(unsigned u) {
    return __uint_as_float((u & 0x80000000u) ? (u & 0x7fffffffu) : ~u);
}

// decode edge e of the concatenated [fwd | reverse | self-loop] edge list (int32)
__device__ __forceinline__ void edge_sd(int e, const int* __restrict__ ei,
                                        int& s, int& d) {
    if (e < EB)          { s = ei[e];              d = ei[EB + e]; }
    else if (e < 2 * EB) { int t = e - EB; s = ei[EB + t]; d = ei[t]; }
    else                 { int t = e - 2 * EB; s = t; d = t; }
}

// ----------------------------- init ---------------------------------------
__global__ void init_k() {
    int i = blockIdx.x * blockDim.x + threadIdx.x;
    if (i < NN * 64) ((float4*)g_agg)[i] = make_float4(0.f, 0.f, 0.f, 0.f);
    if (i < NN * 2) { g_m[i] = 0u; g_s[i] = 0.f; }
    if (i < NN) g_deg[i] = 0.f;
}

// -------- fold W1 through Wkqv: W_comb[k][n], n: 0..255 v | 256..511 pk | 512..767 pq
__global__ void prep_w(const float* __restrict__ Wkqv, const float* __restrict__ bkqv,
                       const float* __restrict__ W1,   const float* __restrict__ b1) {
    const float INVSQ = 0.08838834764831845f;   // 1/sqrt(128)
    int n = blockIdx.x;      // 0..767
    int k = threadIdx.x;     // 0..255
    float val, bval = 0.f;
    if (n < 256) {
        val  = Wkqv[(size_t)k * 768 + 512 + n];          // v block
        bval = bkqv[512 + n];
    } else if (n < 512) {                                 // pk = (k/sqrt)@W1_top
        int h = (n - 256) >> 7, j = (n - 256) & 127;
        int c0 = 256 + h * 128;                           // k columns of Wkqv
        float acc = 0.f;
        for (int m = 0; m < 128; m++)
            acc += Wkqv[(size_t)k * 768 + c0 + m] * W1[m * 128 + j];
        val = acc * INVSQ;
        if (k == 0) {
            float b = 0.f;
            for (int m = 0; m < 128; m++) b += bkqv[c0 + m] * W1[m * 128 + j];
            bval = b * INVSQ;
        }
    } else {                                              // pq = q@W1_bot + b1
        int h = (n - 512) >> 7, j = (n - 512) & 127;
        int c0 = h * 128;                                 // q columns of Wkqv
        float acc = 0.f;
        for (int m = 0; m < 128; m++)
            acc += Wkqv[(size_t)k * 768 + c0 + m] * W1[(128 + m) * 128 + j];
        val = acc;
        if (k == 0) {
            float b = b1[j];
            for (int m = 0; m < 128; m++) b += bkqv[c0 + m] * W1[(128 + m) * 128 + j];
            bval = b;
        }
    }
    g_wcf[(size_t)k * NCOMB + n] = val;
    if (k == 0) g_bcomb[n] = bval;
}

// ----------------------------- SGEMM with packed f32x2 FMA -------------------
// C[M,N] = A[M,K] @ B[K,N] (+ bias per col)
// EPI==1: v = acc + deg[row]*bias[col]; v = relu(v) + x[row,col]
template<int EPI>
__global__ void __launch_bounds__(256, 2)
sgemm(const float* __restrict__ A, int lda,
      const float* __restrict__ B, int ldb,
      float* __restrict__ C, int ldc,
      const float* __restrict__ bias,
      const float* __restrict__ x,
      int M, int K)
{
    __shared__ float As[16][128];
    __shared__ float Bs[16][128];
    const int tid = threadIdx.x;
    const int bm0 = blockIdx.y * 128;
    const int bn0 = blockIdx.x * 128;
    const int tx = tid & 15, ty = tid >> 4;

    // packed accumulators: acc[i][jp] holds cols (2jp, 2jp+1) for row i
    unsigned long long acc[8][4];
    #pragma unroll
    for (int i = 0; i < 8; i++)
        #pragma unroll
        for (int j = 0; j < 4; j++) acc[i][j] = 0ull;

    const int rowA = tid >> 2;          // 0..63
    const int colA = (tid & 3) * 4;     // 0,4,8,12
    const int kB   = tid >> 5;          // 0..7
    const int colB = (tid & 31) * 4;    // 0..124

    for (int k0 = 0; k0 < K; k0 += 16) {
        #pragma unroll
        for (int i = 0; i < 2; i++) {
            int r  = rowA + i * 64;
            int rg = bm0 + r;
            float4 v = make_float4(0.f, 0.f, 0.f, 0.f);
            if (rg < M) v = *(const float4*)(A + (size_t)rg * lda + k0 + colA);
            As[colA + 0][r] = v.x;
            As[colA + 1][r] = v.y;
            As[colA + 2][r] = v.z;
            As[colA + 3][r] = v.w;
        }
        #pragma unroll
        for (int i = 0; i < 2; i++) {
            int kk = kB + i * 8;
            *(float4*)(&Bs[kk][colB]) =
                *(const float4*)(B + (size_t)(k0 + kk) * ldb + bn0 + colB);
        }
        __syncthreads();
        #pragma unroll
        for (int kk = 0; kk < 16; kk++) {
            float af[8];
            *(float4*)(af)     = *(const float4*)(&As[kk][ty * 8]);
            *(float4*)(af + 4) = *(const float4*)(&As[kk][ty * 8 + 4]);
            // B fragment as 4 packed f32x2 (two 16B shared loads)
            ulonglong2 bq01 = *(const ulonglong2*)(&Bs[kk][tx * 8]);
            ulonglong2 bq23 = *(const ulonglong2*)(&Bs[kk][tx * 8 + 4]);
            #pragma unroll
            for (int i = 0; i < 8; i++) {
                unsigned long long ad;
                asm("mov.b64 %0, {%1, %1};" : "=l"(ad) : "f"(af[i]));
                asm("fma.rn.f32x2 %0, %1, %2, %0;" : "+l"(acc[i][0]) : "l"(ad), "l"(bq01.x));
                asm("fma.rn.f32x2 %0, %1, %2, %0;" : "+l"(acc[i][1]) : "l"(ad), "l"(bq01.y));
                asm("fma.rn.f32x2 %0, %1, %2, %0;" : "+l"(acc[i][2]) : "l"(ad), "l"(bq23.x));
                asm("fma.rn.f32x2 %0, %1, %2, %0;" : "+l"(acc[i][3]) : "l"(ad), "l"(bq23.y));
            }
        }
        __syncthreads();
    }

    #pragma unroll
    for (int i = 0; i < 8; i++) {
        int rg = bm0 + ty * 8 + i;
        if (rg >= M) continue;
        float dgb = (EPI == 1) ? g_deg[rg] : 0.f;
        #pragma unroll
        for (int jp = 0; jp < 4; jp++) {
            int cg = bn0 + tx * 8 + 2 * jp;
            float lo, hi;
            asm("mov.b64 {%0, %1}, %2;" : "=f"(lo), "=f"(hi) : "l"(acc[i][jp]));
            if (EPI == 0) {
                lo += bias[cg];
                hi += bias[cg + 1];
            } else {
                lo = fmaxf(lo + dgb * bias[cg],     0.f) + x[(size_t)rg * EMBD + cg];
                hi = fmaxf(hi + dgb * bias[cg + 1], 0.f) + x[(size_t)rg * EMBD + cg + 1];
            }
            *(float2*)(C + (size_t)rg * ldc + cg) = make_float2(lo, hi);
        }
    }
}

// --------------------- edge logits + segment max ----------------------------
__global__ void edge_logits(const int* __restrict__ ei,
                            const float* __restrict__ W2,
                            const float* __restrict__ b2)
{
    int e    = (blockIdx.x * blockDim.x + threadIdx.x) >> 5;
    int lane = threadIdx.x & 31;
    if (e >= ETOT) return;
    int s, d; edge_sd(e, ei, s, d);
    const float4* pk = (const float4*)(g_vpp + (size_t)s * NCOMB + 256);
    const float4* pq = (const float4*)(g_vpp + (size_t)d * NCOMB + 512);
    const float4  wv = ((const float4*)W2)[lane];

    float4 ka = pk[lane],      qa = pq[lane];
    float p0 = fmaxf(ka.x + qa.x, 0.f) * wv.x + fmaxf(ka.y + qa.y, 0.f) * wv.y
             + fmaxf(ka.z + qa.z, 0.f) * wv.z + fmaxf(ka.w + qa.w, 0.f) * wv.w;
    float4 kb = pk[32 + lane], qb = pq[32 + lane];
    float p1 = fmaxf(kb.x + qb.x, 0.f) * wv.x + fmaxf(kb.y + qb.y, 0.f) * wv.y
             + fmaxf(kb.z + qb.z, 0.f) * wv.z + fmaxf(kb.w + qb.w, 0.f) * wv.w;

    #pragma unroll
    for (int o = 16; o > 0; o >>= 1) {
        p0 += __shfl_xor_sync(0xffffffffu, p0, o);
        p1 += __shfl_xor_sync(0xffffffffu, p1, o);
    }
    if (lane == 0) {
        float bb = b2[0];
        float a0 = p0 + bb, a1 = p1 + bb;
        g_a[(size_t)e * 2 + 0] = a0;
        g_a[(size_t)e * 2 + 1] = a1;
        atomicMax(&g_m[d * 2 + 0], fenc(a0));
        atomicMax(&g_m[d * 2 + 1], fenc(a1));
    }
}

// --------------------- exp + segment sum ------------------------------------
__global__ void edge_exp(const int* __restrict__ ei) {
    int t = blockIdx.x * blockDim.x + threadIdx.x;
    if (t >= ETOT * 2) return;
    int e = t >> 1, h = t & 1;
    int s, d; edge_sd(e, ei, s, d);
    float ex = expf(g_a[t] - fdec(g_m[d * 2 + h]));
    g_a[t] = ex;
    atomicAdd(&g_s[d * 2 + h], ex);
    if (h == 0) atomicAdd(&g_deg[d], 1.0f);
}

// --------------------- weighted scatter of v (warp per edge) ----------------
__global__ void edge_agg(const int* __restrict__ ei) {
    int e    = (blockIdx.x * blockDim.x + threadIdx.x) >> 5;
    int lane = threadIdx.x & 31;
    if (e >= ETOT) return;
    int s, d; edge_sd(e, ei, s, d);
    float al0 = g_a[(size_t)e * 2 + 0] / (g_s[d * 2 + 0] + 1e-16f);
    float al1 = g_a[(size_t)e * 2 + 1] / (g_s[d * 2 + 1] + 1e-16f);
    const float4* v = (const float4*)(g_vpp + (size_t)s * NCOMB);
    float4 v0 = v[lane], v1 = v[32 + lane];
    float* dst0 = g_agg + (size_t)d * EMBD + 4 * lane;
    atomicAdd(dst0 + 0, v0.x * al0);
    atomicAdd(dst0 + 1, v0.y * al0);
    atomicAdd(dst0 + 2, v0.z * al0);
    atomicAdd(dst0 + 3, v0.w * al0);
    float* dst1 = dst0 + 128;
    atomicAdd(dst1 + 0, v1.x * al1);
    atomicAdd(dst1 + 1, v1.y * al1);
    atomicAdd(dst1 + 2, v1.z * al1);
    atomicAdd(dst1 + 3, v1.w * al1);
}

// ----------------------------- launch ---------------------------------------
extern "C" void kernel_launch(void* const* d_in, const int* in_sizes, int n_in,
                              void* d_out, int out_size)
{
    const float* x    = (const float*)d_in[0];
    const int*   ei   = (const int*)d_in[1];
    const float* Wkqv = (const float*)d_in[2];
    const float* bkqv = (const float*)d_in[3];
    const float* W1   = (const float*)d_in[4];
    const float* b1   = (const float*)d_in[5];
    const float* W2   = (const float*)d_in[6];
    const float* b2   = (const float*)d_in[7];
    const float* Wout = (const float*)d_in[8];
    const float* bout = (const float*)d_in[9];
    float*       out  = (float*)d_out;

    float *vpp, *wcf, *bcomb, *agg;
    cudaGetSymbolAddress((void**)&vpp,   g_vpp);
    cudaGetSymbolAddress((void**)&wcf,   g_wcf);
    cudaGetSymbolAddress((void**)&bcomb, g_bcomb);
    cudaGetSymbolAddress((void**)&agg,   g_agg);

    const int mtiles = (NN + 127) / 128;   // 391
    dim3 blk(256);

    init_k<<<(NN * 64 + 255) / 256, 256>>>();
    prep_w<<<NCOMB, 256>>>(Wkqv, bkqv, W1, b1);

    // GEMM1: vpp[N,768] = x @ W_comb + b_comb   (v | pk | pq)
    sgemm<0><<<dim3(NCOMB / 128, mtiles), blk>>>(
        x, EMBD, wcf, NCOMB, vpp, NCOMB, bcomb, nullptr, NN, EMBD);

    // edge pipeline
    edge_logits<<<(ETOT + 7) / 8, 256>>>(ei, W2, b2);
    edge_exp<<<(ETOT * 2 + 255) / 256, 256>>>(ei);
    edge_agg<<<(ETOT + 7) / 8, 256>>>(ei);

    // GEMM2: out = relu(agg @ Wout + deg*bout) + x
    sgemm<1><<<dim3(EMBD / 128, mtiles), blk>>>(
        agg, EMBD, Wout, EMBD, out, EMBD, bout, x, NN, EMBD);
}

// round 11
// speedup vs baseline: 2.5876x; 1.9065x over previous
#include <cuda_runtime.h>
#include <cuda_bf16.h>
#include <math.h>
#include <cstdint>

#define NN    50000
#define EMBD  256
#define HD    128
#define EB    100000
#define ETOT  (2*EB + NN)      // 250000 directed edges incl self-loops
#define NCOMB 768              // v(256) | pk(256) | pq(256)

// ------------- persistent device scratch (allocation-free rule) -------------
__device__ __align__(16) float         g_vpp [(size_t)NN * NCOMB]; // [N,768] v|pk|pq (fp32)
__device__ __align__(16) __nv_bfloat16 g_xbf [(size_t)NN * EMBD];  // x in bf16
__device__ __align__(16) __nv_bfloat16 g_wcomb[NCOMB * EMBD];      // [n][k] fused W (bf16)
__device__ float                       g_bcomb[NCOMB];             // fused bias (fp32)
__device__ __align__(16) __nv_bfloat16 g_woutt[EMBD * EMBD];       // [n][k] = Wout[k][n] (bf16)
__device__ __align__(16) float         g_agg [(size_t)NN * EMBD];  // sum alpha*v (fp32)
__device__ __align__(16) __nv_bfloat16 g_aggbf[(size_t)NN * EMBD]; // agg in bf16
__device__ float    g_a  [(size_t)ETOT * 2];
__device__ unsigned g_m  [NN * 2];
__device__ float    g_s  [NN * 2];
__device__ float    g_deg[NN];

// monotone encoding of float for atomicMax on unsigned
__device__ __forceinline__ unsigned fenc(float f) {
    unsigned u = __float_as_uint(f);
    return (u & 0x80000000u) ? ~u : (u | 0x80000000u);
}
__device__ __forceinline__ float fdec(unsigned u) {
    return __uint_as_float((u & 0x80000000u) ? (u & 0x7fffffffu) : ~u);
}

// decode edge e of the concatenated [fwd | reverse | self-loop] edge list (int32)
__device__ __forceinline__ void edge_sd(int e, const int* __restrict__ ei,
                                        int& s, int& d) {
    if (e < EB)          { s = ei[e];              d = ei[EB + e]; }
    else if (e < 2 * EB) { int t = e - EB; s = ei[EB + t]; d = ei[t]; }
    else                 { int t = e - 2 * EB; s = t; d = t; }
}

// ----------------------------- init / converts ------------------------------
__global__ void init_k() {
    int i = blockIdx.x * blockDim.x + threadIdx.x;
    if (i < NN * 64) ((float4*)g_agg)[i] = make_float4(0.f, 0.f, 0.f, 0.f);
    if (i < NN * 2) { g_m[i] = 0u; g_s[i] = 0.f; }
    if (i < NN) g_deg[i] = 0.f;
}

__global__ void conv_x(const float* __restrict__ x) {
    int t = blockIdx.x * blockDim.x + threadIdx.x;
    if (t >= NN * 64) return;
    float4 v = ((const float4*)x)[t];
    __nv_bfloat162* o = (__nv_bfloat162*)g_xbf;
    o[2 * t]     = __floats2bfloat162_rn(v.x, v.y);
    o[2 * t + 1] = __floats2bfloat162_rn(v.z, v.w);
}

__global__ void conv_agg() {
    int t = blockIdx.x * blockDim.x + threadIdx.x;
    if (t >= NN * 64) return;
    float4 v = ((const float4*)g_agg)[t];
    __nv_bfloat162* o = (__nv_bfloat162*)g_aggbf;
    o[2 * t]     = __floats2bfloat162_rn(v.x, v.y);
    o[2 * t + 1] = __floats2bfloat162_rn(v.z, v.w);
}

// -------- fold W1 through Wkqv: W_comb[n][k] bf16; n: 0..255 v | 256..511 pk | 512..767 pq
__global__ void prep_w(const float* __restrict__ Wkqv, const float* __restrict__ bkqv,
                       const float* __restrict__ W1,   const float* __restrict__ b1) {
    const float INVSQ = 0.08838834764831845f;   // 1/sqrt(128)
    int n = blockIdx.x;      // 0..767
    int k = threadIdx.x;     // 0..255
    float val, bval = 0.f;
    if (n < 256) {
        val  = Wkqv[(size_t)k * 768 + 512 + n];          // v block
        bval = bkqv[512 + n];
    } else if (n < 512) {                                 // pk = (k/sqrt)@W1_top
        int h = (n - 256) >> 7, j = (n - 256) & 127;
        int c0 = 256 + h * 128;
        float acc = 0.f;
        for (int m = 0; m < 128; m++)
            acc += Wkqv[(size_t)k * 768 + c0 + m] * W1[m * 128 + j];
        val = acc * INVSQ;
        if (k == 0) {
            float b = 0.f;
            for (int m = 0; m < 128; m++) b += bkqv[c0 + m] * W1[m * 128 + j];
            bval = b * INVSQ;
        }
    } else {                                              // pq = q@W1_bot + b1
        int h = (n - 512) >> 7, j = (n - 512) & 127;
        int c0 = h * 128;
        float acc = 0.f;
        for (int m = 0; m < 128; m++)
            acc += Wkqv[(size_t)k * 768 + c0 + m] * W1[(128 + m) * 128 + j];
        val = acc;
        if (k == 0) {
            float b = b1[j];
            for (int m = 0; m < 128; m++) b += bkqv[c0 + m] * W1[(128 + m) * 128 + j];
            bval = b;
        }
    }
    g_wcomb[(size_t)n * EMBD + k] = __float2bfloat16(val);
    if (k == 0) g_bcomb[n] = bval;
}

__global__ void prep_wout(const float* __restrict__ Wout) {
    int t = blockIdx.x * blockDim.x + threadIdx.x;  // 65536
    int n = t >> 8, k = t & 255;
    g_woutt[t] = __float2bfloat16(Wout[k * 256 + n]);
}

// -------------- bf16 mma.sync GEMM: C[M,N] = A[M,256] @ Bt[N,256]^T --------------
// A row-major bf16 (lda=256), Bt row-major [n][k] bf16.
// EPI 0: C = acc + bias[col]
// EPI 1: C = relu(acc + deg[row]*bias[col]) + x[row,col]
#define SMPAD 40   // padded row stride (elements) -> conflict-free fragment loads

template<int EPI>
__global__ void __launch_bounds__(256)
gemm_mma(const __nv_bfloat16* __restrict__ A,
         const __nv_bfloat16* __restrict__ Bt,
         float* __restrict__ C, int ldc,
         const float* __restrict__ bias,
         const float* __restrict__ x, int M)
{
    __shared__ __align__(16) __nv_bfloat16 As[128][SMPAD];
    __shared__ __align__(16) __nv_bfloat16 Bs[128][SMPAD];

    const int tid  = threadIdx.x;
    const int warp = tid >> 5, lane = tid & 31;
    const int g = lane >> 2, t = lane & 3;         // mma group / thread-in-group
    const int wm = warp & 1, wn = warp >> 1;       // 2 x 4 warp grid
    const int bm0 = blockIdx.y * 128, bn0 = blockIdx.x * 128;

    float c[4][4][4];
    #pragma unroll
    for (int mi = 0; mi < 4; mi++)
        #pragma unroll
        for (int ni = 0; ni < 4; ni++)
            #pragma unroll
            for (int r = 0; r < 4; r++) c[mi][ni][r] = 0.f;

    for (int k0 = 0; k0 < 256; k0 += 32) {
        // stage 128x32 of A and Bt
        #pragma unroll
        for (int i = 0; i < 2; i++) {
            int idx = tid + i * 256;               // 0..511
            int r = idx >> 2, q = idx & 3;
            uint4 av = make_uint4(0u, 0u, 0u, 0u);
            if (bm0 + r < M)
                av = *(const uint4*)(A + (size_t)(bm0 + r) * 256 + k0 + q * 8);
            *(uint4*)(&As[r][q * 8]) = av;
            uint4 bv = *(const uint4*)(Bt + (size_t)(bn0 + r) * 256 + k0 + q * 8);
            *(uint4*)(&Bs[r][q * 8]) = bv;
        }
        __syncthreads();

        #pragma unroll
        for (int sub = 0; sub < 2; sub++) {
            int ks = sub * 16 + t * 2;
            uint32_t a[4][4], b[4][2];
            #pragma unroll
            for (int mi = 0; mi < 4; mi++) {
                int r0 = wm * 64 + mi * 16 + g;
                a[mi][0] = *(const uint32_t*)(&As[r0][ks]);
                a[mi][1] = *(const uint32_t*)(&As[r0 + 8][ks]);
                a[mi][2] = *(const uint32_t*)(&As[r0][ks + 8]);
                a[mi][3] = *(const uint32_t*)(&As[r0 + 8][ks + 8]);
            }
            #pragma unroll
            for (int ni = 0; ni < 4; ni++) {
                int n0 = wn * 32 + ni * 8 + g;
                b[ni][0] = *(const uint32_t*)(&Bs[n0][ks]);
                b[ni][1] = *(const uint32_t*)(&Bs[n0][ks + 8]);
            }
            #pragma unroll
            for (int mi = 0; mi < 4; mi++)
                #pragma unroll
                for (int ni = 0; ni < 4; ni++)
                    asm volatile(
                        "mma.sync.aligned.m16n8k16.row.col.f32.bf16.bf16.f32 "
                        "{%0,%1,%2,%3}, {%4,%5,%6,%7}, {%8,%9}, {%0,%1,%2,%3};"
                        : "+f"(c[mi][ni][0]), "+f"(c[mi][ni][1]),
                          "+f"(c[mi][ni][2]), "+f"(c[mi][ni][3])
                        : "r"(a[mi][0]), "r"(a[mi][1]), "r"(a[mi][2]), "r"(a[mi][3]),
                          "r"(b[ni][0]), "r"(b[ni][1]));
        }
        __syncthreads();
    }

    // epilogue
    #pragma unroll
    for (int mi = 0; mi < 4; mi++) {
        int r0 = bm0 + wm * 64 + mi * 16 + g;      // rows r0 and r0+8
        #pragma unroll
        for (int ni = 0; ni < 4; ni++) {
            int cc = bn0 + wn * 32 + ni * 8 + t * 2;
            float b0 = bias[cc], b1v = bias[cc + 1];
            if (r0 < M) {
                float lo = c[mi][ni][0], hi = c[mi][ni][1];
                if (EPI == 0) { lo += b0; hi += b1v; }
                else {
                    float dg = g_deg[r0];
                    lo = fmaxf(lo + dg * b0,  0.f) + x[(size_t)r0 * EMBD + cc];
                    hi = fmaxf(hi + dg * b1v, 0.f) + x[(size_t)r0 * EMBD + cc + 1];
                }
                *(float2*)(C + (size_t)r0 * ldc + cc) = make_float2(lo, hi);
            }
            int r1 = r0 + 8;
            if (r1 < M) {
                float lo = c[mi][ni][2], hi = c[mi][ni][3];
                if (EPI == 0) { lo += b0; hi += b1v; }
                else {
                    float dg = g_deg[r1];
                    lo = fmaxf(lo + dg * b0,  0.f) + x[(size_t)r1 * EMBD + cc];
                    hi = fmaxf(hi + dg * b1v, 0.f) + x[(size_t)r1 * EMBD + cc + 1];
                }
                *(float2*)(C + (size_t)r1 * ldc + cc) = make_float2(lo, hi);
            }
        }
    }
}

// --------------------- edge logits + segment max ----------------------------
__global__ void edge_logits(const int* __restrict__ ei,
                            const float* __restrict__ W2,
                            const float* __restrict__ b2)
{
    int e    = (blockIdx.x * blockDim.x + threadIdx.x) >> 5;
    int lane = threadIdx.x & 31;
    if (e >= ETOT) return;
    int s, d; edge_sd(e, ei, s, d);
    const float4* pk = (const float4*)(g_vpp + (size_t)s * NCOMB + 256);
    const float4* pq = (const float4*)(g_vpp + (size_t)d * NCOMB + 512);
    const float4  wv = ((const float4*)W2)[lane];

    float4 ka = pk[lane],      qa = pq[lane];
    float p0 = fmaxf(ka.x + qa.x, 0.f) * wv.x + fmaxf(ka.y + qa.y, 0.f) * wv.y
             + fmaxf(ka.z + qa.z, 0.f) * wv.z + fmaxf(ka.w + qa.w, 0.f) * wv.w;
    float4 kb = pk[32 + lane], qb = pq[32 + lane];
    float p1 = fmaxf(kb.x + qb.x, 0.f) * wv.x + fmaxf(kb.y + qb.y, 0.f) * wv.y
             + fmaxf(kb.z + qb.z, 0.f) * wv.z + fmaxf(kb.w + qb.w, 0.f) * wv.w;

    #pragma unroll
    for (int o = 16; o > 0; o >>= 1) {
        p0 += __shfl_xor_sync(0xffffffffu, p0, o);
        p1 += __shfl_xor_sync(0xffffffffu, p1, o);
    }
    if (lane == 0) {
        float bb = b2[0];
        float a0 = p0 + bb, a1 = p1 + bb;
        g_a[(size_t)e * 2 + 0] = a0;
        g_a[(size_t)e * 2 + 1] = a1;
        atomicMax(&g_m[d * 2 + 0], fenc(a0));
        atomicMax(&g_m[d * 2 + 1], fenc(a1));
    }
}

// --------------------- exp + segment sum ------------------------------------
__global__ void edge_exp(const int* __restrict__ ei) {
    int t = blockIdx.x * blockDim.x + threadIdx.x;
    if (t >= ETOT * 2) return;
    int e = t >> 1, h = t & 1;
    int s, d; edge_sd(e, ei, s, d);
    float ex = expf(g_a[t] - fdec(g_m[d * 2 + h]));
    g_a[t] = ex;
    atomicAdd(&g_s[d * 2 + h], ex);
    if (h == 0) atomicAdd(&g_deg[d], 1.0f);
}

// --------------------- weighted scatter of v (warp per edge) ----------------
__global__ void edge_agg(const int* __restrict__ ei) {
    int e    = (blockIdx.x * blockDim.x + threadIdx.x) >> 5;
    int lane = threadIdx.x & 31;
    if (e >= ETOT) return;
    int s, d; edge_sd(e, ei, s, d);
    float al0 = g_a[(size_t)e * 2 + 0] / (g_s[d * 2 + 0] + 1e-16f);
    float al1 = g_a[(size_t)e * 2 + 1] / (g_s[d * 2 + 1] + 1e-16f);
    const float4* v = (const float4*)(g_vpp + (size_t)s * NCOMB);
    float4 v0 = v[lane], v1 = v[32 + lane];
    float* dst0 = g_agg + (size_t)d * EMBD + 4 * lane;
    atomicAdd(dst0 + 0, v0.x * al0);
    atomicAdd(dst0 + 1, v0.y * al0);
    atomicAdd(dst0 + 2, v0.z * al0);
    atomicAdd(dst0 + 3, v0.w * al0);
    float* dst1 = dst0 + 128;
    atomicAdd(dst1 + 0, v1.x * al1);
    atomicAdd(dst1 + 1, v1.y * al1);
    atomicAdd(dst1 + 2, v1.z * al1);
    atomicAdd(dst1 + 3, v1.w * al1);
}

// ----------------------------- launch ---------------------------------------
extern "C" void kernel_launch(void* const* d_in, const int* in_sizes, int n_in,
                              void* d_out, int out_size)
{
    const float* x    = (const float*)d_in[0];
    const int*   ei   = (const int*)d_in[1];
    const float* Wkqv = (const float*)d_in[2];
    const float* bkqv = (const float*)d_in[3];
    const float* W1   = (const float*)d_in[4];
    const float* b1   = (const float*)d_in[5];
    const float* W2   = (const float*)d_in[6];
    const float* b2   = (const float*)d_in[7];
    const float* Wout = (const float*)d_in[8];
    const float* bout = (const float*)d_in[9];
    float*       out  = (float*)d_out;

    float *vpp, *bcomb;
    __nv_bfloat16 *xbf, *wcomb, *woutt, *aggbf;
    cudaGetSymbolAddress((void**)&vpp,   g_vpp);
    cudaGetSymbolAddress((void**)&bcomb, g_bcomb);
    cudaGetSymbolAddress((void**)&xbf,   g_xbf);
    cudaGetSymbolAddress((void**)&wcomb, g_wcomb);
    cudaGetSymbolAddress((void**)&woutt, g_woutt);
    cudaGetSymbolAddress((void**)&aggbf, g_aggbf);

    const int mtiles = (NN + 127) / 128;   // 391

    init_k<<<(NN * 64 + 255) / 256, 256>>>();
    conv_x<<<(NN * 64 + 255) / 256, 256>>>(x);
    prep_w<<<NCOMB, 256>>>(Wkqv, bkqv, W1, b1);
    prep_wout<<<256, 256>>>(Wout);

    // GEMM1: vpp[N,768] = x_bf @ W_comb^T + b_comb   (v | pk | pq)
    gemm_mma<0><<<dim3(NCOMB / 128, mtiles), 256>>>(
        xbf, wcomb, vpp, NCOMB, bcomb, nullptr, NN);

    // edge pipeline
    edge_logits<<<(ETOT + 7) / 8, 256>>>(ei, W2, b2);
    edge_exp<<<(ETOT * 2 + 255) / 256, 256>>>(ei);
    edge_agg<<<(ETOT + 7) / 8, 256>>>(ei);

    conv_agg<<<(NN * 64 + 255) / 256, 256>>>();

    // GEMM2: out = relu(agg_bf @ Wout^T + deg*bout) + x
    gemm_mma<1><<<dim3(EMBD / 128, mtiles), 256>>>(
        aggbf, woutt, out, EMBD, bout, x, NN);
}

// round 12
// speedup vs baseline: 3.2455x; 1.2543x over previous
#include <cuda_runtime.h>
#include <cuda_bf16.h>
#include <math.h>
#include <cstdint>

#define NN    50000
#define EMBD  256
#define HD    128
#define EB    100000
#define ETOT  (2*EB + NN)      // 250000 directed edges incl self-loops
#define NCOMB 768              // v(256) | pk(256) | pq(256)

// ------------- persistent device scratch (allocation-free rule) -------------
__device__ __align__(16) __nv_bfloat16 g_vppbf[(size_t)NN * NCOMB]; // [N,768] v|pk|pq bf16
__device__ __align__(16) __nv_bfloat16 g_xbf [(size_t)NN * EMBD];   // x in bf16
__device__ __align__(16) __nv_bfloat16 g_wcomb[NCOMB * EMBD];       // [n][k] fused W bf16
__device__ float                       g_bcomb[NCOMB];              // fused bias fp32
__device__ __align__(16) __nv_bfloat16 g_woutt[EMBD * EMBD];        // [n][k] = Wout[k][n] bf16
__device__ __align__(16) float         g_agg [(size_t)NN * EMBD];   // sum alpha*v fp32
__device__ float g_a  [(size_t)ETOT * 2];   // exp(logit) per edge-head
__device__ float g_s  [NN * 2];             // segment sum of exp
__device__ float g_deg[NN];                 // in-degree

// decode edge e of the concatenated [fwd | reverse | self-loop] edge list (int32)
__device__ __forceinline__ void edge_sd(int e, const int* __restrict__ ei,
                                        int& s, int& d) {
    if (e < EB)          { s = ei[e];              d = ei[EB + e]; }
    else if (e < 2 * EB) { int t = e - EB; s = ei[EB + t]; d = ei[t]; }
    else                 { int t = e - 2 * EB; s = t; d = t; }
}

// ----------------------------- init / converts ------------------------------
__global__ void init_k() {
    int i = blockIdx.x * blockDim.x + threadIdx.x;
    if (i < NN * 64) ((float4*)g_agg)[i] = make_float4(0.f, 0.f, 0.f, 0.f);
    if (i < NN * 2) g_s[i] = 0.f;
    if (i < NN) g_deg[i] = 0.f;
}

__global__ void conv_x(const float* __restrict__ x) {
    int t = blockIdx.x * blockDim.x + threadIdx.x;
    if (t >= NN * 64) return;
    float4 v = ((const float4*)x)[t];
    __nv_bfloat162* o = (__nv_bfloat162*)g_xbf;
    o[2 * t]     = __floats2bfloat162_rn(v.x, v.y);
    o[2 * t + 1] = __floats2bfloat162_rn(v.z, v.w);
}

// -------- fold W1 through Wkqv: W_comb[n][k] bf16; n: 0..255 v | 256..511 pk | 512..767 pq
__global__ void prep_w(const float* __restrict__ Wkqv, const float* __restrict__ bkqv,
                       const float* __restrict__ W1,   const float* __restrict__ b1) {
    const float INVSQ = 0.08838834764831845f;   // 1/sqrt(128)
    int n = blockIdx.x;      // 0..767
    int k = threadIdx.x;     // 0..255
    float val, bval = 0.f;
    if (n < 256) {
        val  = Wkqv[(size_t)k * 768 + 512 + n];          // v block
        bval = bkqv[512 + n];
    } else if (n < 512) {                                 // pk = (k/sqrt)@W1_top
        int h = (n - 256) >> 7, j = (n - 256) & 127;
        int c0 = 256 + h * 128;
        float acc = 0.f;
        for (int m = 0; m < 128; m++)
            acc += Wkqv[(size_t)k * 768 + c0 + m] * W1[m * 128 + j];
        val = acc * INVSQ;
        if (k == 0) {
            float b = 0.f;
            for (int m = 0; m < 128; m++) b += bkqv[c0 + m] * W1[m * 128 + j];
            bval = b * INVSQ;
        }
    } else {                                              // pq = q@W1_bot + b1
        int h = (n - 512) >> 7, j = (n - 512) & 127;
        int c0 = h * 128;
        float acc = 0.f;
        for (int m = 0; m < 128; m++)
            acc += Wkqv[(size_t)k * 768 + c0 + m] * W1[(128 + m) * 128 + j];
        val = acc;
        if (k == 0) {
            float b = b1[j];
            for (int m = 0; m < 128; m++) b += bkqv[c0 + m] * W1[(128 + m) * 128 + j];
            bval = b;
        }
    }
    g_wcomb[(size_t)n * EMBD + k] = __float2bfloat16(val);
    if (k == 0) g_bcomb[n] = bval;
}

__global__ void prep_wout(const float* __restrict__ Wout) {
    int t = blockIdx.x * blockDim.x + threadIdx.x;  // 65536
    int n = t >> 8, k = t & 255;
    g_woutt[t] = __float2bfloat16(Wout[k * 256 + n]);
}

// -------------- bf16 mma.sync GEMM: C[M,N] = A[M,256] @ Bt[N,256]^T --------------
// MODE 0: A bf16 in, C bf16 out = acc + bias[col]            (GEMM1)
// MODE 1: A fp32 in (converted while staging), C fp32 out =
//         relu(acc + deg[row]*bias[col]) + x[row,col]        (GEMM2)
#define SMPAD 40   // padded row stride (elements) -> conflict-free fragment loads

template<int MODE>
__global__ void __launch_bounds__(256)
gemm_mma(const void* __restrict__ Av,
         const __nv_bfloat16* __restrict__ Bt,
         void* __restrict__ Cv, int ldc,
         const float* __restrict__ bias,
         const float* __restrict__ x, int M)
{
    __shared__ __align__(16) __nv_bfloat16 As[128][SMPAD];
    __shared__ __align__(16) __nv_bfloat16 Bs[128][SMPAD];

    const int tid  = threadIdx.x;
    const int warp = tid >> 5, lane = tid & 31;
    const int g = lane >> 2, t = lane & 3;
    const int wm = warp & 1, wn = warp >> 1;       // 2 x 4 warp grid
    const int bm0 = blockIdx.y * 128, bn0 = blockIdx.x * 128;

    float c[4][4][4];
    #pragma unroll
    for (int mi = 0; mi < 4; mi++)
        #pragma unroll
        for (int ni = 0; ni < 4; ni++)
            #pragma unroll
            for (int r = 0; r < 4; r++) c[mi][ni][r] = 0.f;

    for (int k0 = 0; k0 < 256; k0 += 32) {
        #pragma unroll
        for (int i = 0; i < 2; i++) {
            int idx = tid + i * 256;               // 0..511
            int r = idx >> 2, q = idx & 3;
            int row = bm0 + r;
            uint4 av = make_uint4(0u, 0u, 0u, 0u);
            if (row < M) {
                if (MODE == 0) {
                    av = *(const uint4*)((const __nv_bfloat16*)Av +
                                         (size_t)row * 256 + k0 + q * 8);
                } else {
                    const float* Af = (const float*)Av + (size_t)row * 256 + k0 + q * 8;
                    float4 f0 = *(const float4*)(Af);
                    float4 f1 = *(const float4*)(Af + 4);
                    __nv_bfloat162 p0 = __floats2bfloat162_rn(f0.x, f0.y);
                    __nv_bfloat162 p1 = __floats2bfloat162_rn(f0.z, f0.w);
                    __nv_bfloat162 p2 = __floats2bfloat162_rn(f1.x, f1.y);
                    __nv_bfloat162 p3 = __floats2bfloat162_rn(f1.z, f1.w);
                    av = make_uint4(*(uint32_t*)&p0, *(uint32_t*)&p1,
                                    *(uint32_t*)&p2, *(uint32_t*)&p3);
                }
            }
            *(uint4*)(&As[r][q * 8]) = av;
            uint4 bv = *(const uint4*)(Bt + (size_t)(bn0 + r) * 256 + k0 + q * 8);
            *(uint4*)(&Bs[r][q * 8]) = bv;
        }
        __syncthreads();

        #pragma unroll
        for (int sub = 0; sub < 2; sub++) {
            int ks = sub * 16 + t * 2;
            uint32_t a[4][4], b[4][2];
            #pragma unroll
            for (int mi = 0; mi < 4; mi++) {
                int r0 = wm * 64 + mi * 16 + g;
                a[mi][0] = *(const uint32_t*)(&As[r0][ks]);
                a[mi][1] = *(const uint32_t*)(&As[r0 + 8][ks]);
                a[mi][2] = *(const uint32_t*)(&As[r0][ks + 8]);
                a[mi][3] = *(const uint32_t*)(&As[r0 + 8][ks + 8]);
            }
            #pragma unroll
            for (int ni = 0; ni < 4; ni++) {
                int n0 = wn * 32 + ni * 8 + g;
                b[ni][0] = *(const uint32_t*)(&Bs[n0][ks]);
                b[ni][1] = *(const uint32_t*)(&Bs[n0][ks + 8]);
            }
            #pragma unroll
            for (int mi = 0; mi < 4; mi++)
                #pragma unroll
                for (int ni = 0; ni < 4; ni++)
                    asm volatile(
                        "mma.sync.aligned.m16n8k16.row.col.f32.bf16.bf16.f32 "
                        "{%0,%1,%2,%3}, {%4,%5,%6,%7}, {%8,%9}, {%0,%1,%2,%3};"
                        : "+f"(c[mi][ni][0]), "+f"(c[mi][ni][1]),
                          "+f"(c[mi][ni][2]), "+f"(c[mi][ni][3])
                        : "r"(a[mi][0]), "r"(a[mi][1]), "r"(a[mi][2]), "r"(a[mi][3]),
                          "r"(b[ni][0]), "r"(b[ni][1]));
        }
        __syncthreads();
    }

    // epilogue
    #pragma unroll
    for (int mi = 0; mi < 4; mi++) {
        int rbase = bm0 + wm * 64 + mi * 16 + g;
        #pragma unroll
        for (int ni = 0; ni < 4; ni++) {
            int cc = bn0 + wn * 32 + ni * 8 + t * 2;
            float b0 = bias[cc], b1v = bias[cc + 1];
            #pragma unroll
            for (int half = 0; half < 2; half++) {
                int rg = rbase + half * 8;
                if (rg >= M) continue;
                float lo = c[mi][ni][half * 2], hi = c[mi][ni][half * 2 + 1];
                if (MODE == 0) {
                    lo += b0; hi += b1v;
                    __nv_bfloat162 pv = __floats2bfloat162_rn(lo, hi);
                    *(uint32_t*)((__nv_bfloat16*)Cv + (size_t)rg * ldc + cc) =
                        *(uint32_t*)&pv;
                } else {
                    float dg = g_deg[rg];
                    lo = fmaxf(lo + dg * b0,  0.f) + x[(size_t)rg * EMBD + cc];
                    hi = fmaxf(hi + dg * b1v, 0.f) + x[(size_t)rg * EMBD + cc + 1];
                    *(float2*)((float*)Cv + (size_t)rg * ldc + cc) = make_float2(lo, hi);
                }
            }
        }
    }
}

// ------------- fused edge logits + exp + segment sum + degree ---------------
// one warp per edge; lane covers 8 contiguous cols of [pk|pq] (cols 0..255,
// head = col>>7). No max-subtraction: logits ~ O(0.02), exp is safe.
__global__ void edge_logexp(const int* __restrict__ ei,
                            const float* __restrict__ W2,
                            const float* __restrict__ b2)
{
    int e    = (blockIdx.x * blockDim.x + threadIdx.x) >> 5;
    int lane = threadIdx.x & 31;
    if (e >= ETOT) return;
    int s, d; edge_sd(e, ei, s, d);

    const uint4* pk = (const uint4*)(g_vppbf + (size_t)s * NCOMB + 256);
    const uint4* pq = (const uint4*)(g_vppbf + (size_t)d * NCOMB + 512);
    uint4 ku = pk[lane];
    uint4 qu = pq[lane];
    int j = lane & 15;                         // W2 block (cols mod 128)
    float4 w0 = ((const float4*)W2)[j * 2];
    float4 w1 = ((const float4*)W2)[j * 2 + 1];

    const __nv_bfloat162* kp = (const __nv_bfloat162*)&ku;
    const __nv_bfloat162* qp = (const __nv_bfloat162*)&qu;
    float2 k0 = __bfloat1622float2(kp[0]), q0 = __bfloat1622float2(qp[0]);
    float2 k1 = __bfloat1622float2(kp[1]), q1 = __bfloat1622float2(qp[1]);
    float2 k2 = __bfloat1622float2(kp[2]), q2 = __bfloat1622float2(qp[2]);
    float2 k3 = __bfloat1622float2(kp[3]), q3 = __bfloat1622float2(qp[3]);

    float p = fmaxf(k0.x + q0.x, 0.f) * w0.x + fmaxf(k0.y + q0.y, 0.f) * w0.y
            + fmaxf(k1.x + q1.x, 0.f) * w0.z + fmaxf(k1.y + q1.y, 0.f) * w0.w
            + fmaxf(k2.x + q2.x, 0.f) * w1.x + fmaxf(k2.y + q2.y, 0.f) * w1.y
            + fmaxf(k3.x + q3.x, 0.f) * w1.z + fmaxf(k3.y + q3.y, 0.f) * w1.w;

    // reduce within each 16-lane half (head 0: lanes 0-15, head 1: lanes 16-31)
    #pragma unroll
    for (int o = 1; o <= 8; o <<= 1)
        p += __shfl_xor_sync(0xffffffffu, p, o);

    if ((lane & 15) == 0) {
        int h = lane >> 4;
        float ex = expf(p + b2[0]);
        g_a[(size_t)e * 2 + h] = ex;
        atomicAdd(&g_s[d * 2 + h], ex);
        if (lane == 0) atomicAdd(&g_deg[d], 1.0f);
    }
}

// --------------------- weighted scatter of v (warp per edge) ----------------
__global__ void edge_agg(const int* __restrict__ ei) {
    int e    = (blockIdx.x * blockDim.x + threadIdx.x) >> 5;
    int lane = threadIdx.x & 31;
    if (e >= ETOT) return;
    int s, d; edge_sd(e, ei, s, d);
    float al0 = g_a[(size_t)e * 2 + 0] / (g_s[d * 2 + 0] + 1e-16f);
    float al1 = g_a[(size_t)e * 2 + 1] / (g_s[d * 2 + 1] + 1e-16f);
    float al = (lane < 16) ? al0 : al1;        // lane covers cols 8*lane..8*lane+7

    uint4 vu = ((const uint4*)(g_vppbf + (size_t)s * NCOMB))[lane];
    const __nv_bfloat162* vp = (const __nv_bfloat162*)&vu;
    float2 v0 = __bfloat1622float2(vp[0]);
    float2 v1 = __bfloat1622float2(vp[1]);
    float2 v2 = __bfloat1622float2(vp[2]);
    float2 v3 = __bfloat1622float2(vp[3]);

    float* dst = g_agg + (size_t)d * EMBD + 8 * lane;
    asm volatile("red.global.add.v4.f32 [%0], {%1,%2,%3,%4};"
        :: "l"(dst), "f"(v0.x * al), "f"(v0.y * al), "f"(v1.x * al), "f"(v1.y * al)
        : "memory");
    asm volatile("red.global.add.v4.f32 [%0], {%1,%2,%3,%4};"
        :: "l"(dst + 4), "f"(v2.x * al), "f"(v2.y * al), "f"(v3.x * al), "f"(v3.y * al)
        : "memory");
}

// ----------------------------- launch ---------------------------------------
extern "C" void kernel_launch(void* const* d_in, const int* in_sizes, int n_in,
                              void* d_out, int out_size)
{
    const float* x    = (const float*)d_in[0];
    const int*   ei   = (const int*)d_in[1];
    const float* Wkqv = (const float*)d_in[2];
    const float* bkqv = (const float*)d_in[3];
    const float* W1   = (const float*)d_in[4];
    const float* b1   = (const float*)d_in[5];
    const float* W2   = (const float*)d_in[6];
    const float* b2   = (const float*)d_in[7];
    const float* Wout = (const float*)d_in[8];
    const float* bout = (const float*)d_in[9];
    float*       out  = (float*)d_out;

    float *bcomb, *agg;
    __nv_bfloat16 *xbf, *wcomb, *woutt, *vppbf;
    cudaGetSymbolAddress((void**)&vppbf, g_vppbf);
    cudaGetSymbolAddress((void**)&bcomb, g_bcomb);
    cudaGetSymbolAddress((void**)&xbf,   g_xbf);
    cudaGetSymbolAddress((void**)&wcomb, g_wcomb);
    cudaGetSymbolAddress((void**)&woutt, g_woutt);
    cudaGetSymbolAddress((void**)&agg,   g_agg);

    const int mtiles = (NN + 127) / 128;   // 391

    init_k<<<(NN * 64 + 255) / 256, 256>>>();
    conv_x<<<(NN * 64 + 255) / 256, 256>>>(x);
    prep_w<<<NCOMB, 256>>>(Wkqv, bkqv, W1, b1);
    prep_wout<<<256, 256>>>(Wout);

    // GEMM1: vppbf[N,768] = bf16(x_bf @ W_comb^T + b_comb)   (v | pk | pq)
    gemm_mma<0><<<dim3(NCOMB / 128, mtiles), 256>>>(
        xbf, wcomb, vppbf, NCOMB, bcomb, nullptr, NN);

    // fused edge logits+exp+segsum+deg, then weighted scatter
    edge_logexp<<<(ETOT + 7) / 8, 256>>>(ei, W2, b2);
    edge_agg<<<(ETOT + 7) / 8, 256>>>(ei);

    // GEMM2: out = relu(agg @ Wout^T + deg*bout) + x  (agg converted in-kernel)
    gemm_mma<1><<<dim3(EMBD / 128, mtiles), 256>>>(
        agg, woutt, out, EMBD, bout, x, NN);
}

// round 13
// speedup vs baseline: 3.2932x; 1.0147x over previous
#include <cuda_runtime.h>
#include <cuda_bf16.h>
#include <math.h>
#include <cstdint>

#define NN    50000
#define EMBD  256
#define HD    128
#define EB    100000
#define ETOT  (2*EB + NN)      // 250000 directed edges incl self-loops
#define NCOMB 768              // v(256) | pk(256) | pq(256)

// ------------- persistent device scratch (allocation-free rule) -------------
__device__ __align__(16) __nv_bfloat16 g_vppbf[(size_t)NN * NCOMB]; // [N,768] v|pk|pq bf16
__device__ __align__(16) __nv_bfloat16 g_xbf [(size_t)NN * EMBD];   // x in bf16
__device__ __align__(16) __nv_bfloat16 g_wcomb[NCOMB * EMBD];       // [n][k] fused W bf16
__device__ float                       g_bcomb[NCOMB];              // fused bias fp32
__device__ __align__(16) __nv_bfloat16 g_woutt[EMBD * EMBD];        // [n][k] = Wout[k][n] bf16
__device__ __align__(16) float         g_agg [(size_t)NN * EMBD];   // sum alpha*v fp32
__device__ float g_a  [(size_t)ETOT * 2];   // exp(logit) per edge-head
__device__ float g_s  [NN * 2];             // segment sum of exp
__device__ float g_deg[NN];                 // in-degree

// decode edge e of the concatenated [fwd | reverse | self-loop] edge list (int32)
__device__ __forceinline__ void edge_sd(int e, const int* __restrict__ ei,
                                        int& s, int& d) {
    if (e < EB)          { s = ei[e];              d = ei[EB + e]; }
    else if (e < 2 * EB) { int t = e - EB; s = ei[EB + t]; d = ei[t]; }
    else                 { int t = e - 2 * EB; s = t; d = t; }
}

// ----------------------------- init / converts ------------------------------
__global__ void init_k() {
    int i = blockIdx.x * blockDim.x + threadIdx.x;
    if (i < NN * 64) ((float4*)g_agg)[i] = make_float4(0.f, 0.f, 0.f, 0.f);
    if (i < NN * 2) g_s[i] = 0.f;
    if (i < NN) g_deg[i] = 0.f;
}

__global__ void conv_x(const float* __restrict__ x) {
    int t = blockIdx.x * blockDim.x + threadIdx.x;
    if (t >= NN * 64) return;
    float4 v = ((const float4*)x)[t];
    __nv_bfloat162* o = (__nv_bfloat162*)g_xbf;
    o[2 * t]     = __floats2bfloat162_rn(v.x, v.y);
    o[2 * t + 1] = __floats2bfloat162_rn(v.z, v.w);
}

// -------- fold W1 through Wkqv: W_comb[n][k] bf16; n: 0..255 v | 256..511 pk | 512..767 pq
__global__ void prep_w(const float* __restrict__ Wkqv, const float* __restrict__ bkqv,
                       const float* __restrict__ W1,   const float* __restrict__ b1) {
    const float INVSQ = 0.08838834764831845f;   // 1/sqrt(128)
    int n = blockIdx.x;      // 0..767
    int k = threadIdx.x;     // 0..255
    float val, bval = 0.f;
    if (n < 256) {
        val  = Wkqv[(size_t)k * 768 + 512 + n];          // v block
        bval = bkqv[512 + n];
    } else if (n < 512) {                                 // pk = (k/sqrt)@W1_top
        int h = (n - 256) >> 7, j = (n - 256) & 127;
        int c0 = 256 + h * 128;
        float acc = 0.f;
        for (int m = 0; m < 128; m++)
            acc += Wkqv[(size_t)k * 768 + c0 + m] * W1[m * 128 + j];
        val = acc * INVSQ;
        if (k == 0) {
            float b = 0.f;
            for (int m = 0; m < 128; m++) b += bkqv[c0 + m] * W1[m * 128 + j];
            bval = b * INVSQ;
        }
    } else {                                              // pq = q@W1_bot + b1
        int h = (n - 512) >> 7, j = (n - 512) & 127;
        int c0 = h * 128;
        float acc = 0.f;
        for (int m = 0; m < 128; m++)
            acc += Wkqv[(size_t)k * 768 + c0 + m] * W1[(128 + m) * 128 + j];
        val = acc;
        if (k == 0) {
            float b = b1[j];
            for (int m = 0; m < 128; m++) b += bkqv[c0 + m] * W1[(128 + m) * 128 + j];
            bval = b;
        }
    }
    g_wcomb[(size_t)n * EMBD + k] = __float2bfloat16(val);
    if (k == 0) g_bcomb[n] = bval;
}

__global__ void prep_wout(const float* __restrict__ Wout) {
    int t = blockIdx.x * blockDim.x + threadIdx.x;  // 65536
    int n = t >> 8, k = t & 255;
    g_woutt[t] = __float2bfloat16(Wout[k * 256 + n]);
}

// -------------- bf16 mma.sync GEMM, register double-buffered ----------------
// C[M,N] = A[M,256] @ Bt[N,256]^T
// MODE 0: A bf16 in, C bf16 out = acc + bias[col]            (GEMM1)
// MODE 1: A fp32 in (converted at smem store), C fp32 out =
//         relu(acc + deg[row]*bias[col]) + x[row,col]        (GEMM2)
#define SMPAD 40   // padded row stride (elements) -> conflict-free fragment loads

template<int MODE>
__global__ void __launch_bounds__(256)
gemm_mma(const void* __restrict__ Av,
         const __nv_bfloat16* __restrict__ Bt,
         void* __restrict__ Cv, int ldc,
         const float* __restrict__ bias,
         const float* __restrict__ x, int M)
{
    __shared__ __align__(16) __nv_bfloat16 As[128][SMPAD];
    __shared__ __align__(16) __nv_bfloat16 Bs[128][SMPAD];

    const int tid  = threadIdx.x;
    const int warp = tid >> 5, lane = tid & 31;
    const int g = lane >> 2, t = lane & 3;
    const int wm = warp & 1, wn = warp >> 1;       // 2 x 4 warp grid
    const int bm0 = blockIdx.y * 128, bn0 = blockIdx.x * 128;

    // staging coords: thread covers rows rS and rS+64, 8-col chunk qS
    const int rS = tid >> 2, qS = (tid & 3) * 8;
    const bool ok0 = (bm0 + rS)      < M;
    const bool ok1 = (bm0 + rS + 64) < M;

    float c[4][4][4];
    #pragma unroll
    for (int mi = 0; mi < 4; mi++)
        #pragma unroll
        for (int ni = 0; ni < 4; ni++)
            #pragma unroll
            for (int r = 0; r < 4; r++) c[mi][ni][r] = 0.f;

    // prefetch registers
    uint4 pa0, pa1, pb0, pb1;
    float4 pf00, pf01, pf10, pf11;
    const uint4 zero4 = make_uint4(0u, 0u, 0u, 0u);

    // ---- tile load into registers (LDGs only) ----
    #define LOAD_TILE(K0)                                                         \
    do {                                                                          \
        if (MODE == 0) {                                                          \
            pa0 = ok0 ? *(const uint4*)((const __nv_bfloat16*)Av +                \
                      (size_t)(bm0 + rS) * 256 + (K0) + qS) : zero4;              \
            pa1 = ok1 ? *(const uint4*)((const __nv_bfloat16*)Av +                \
                      (size_t)(bm0 + rS + 64) * 256 + (K0) + qS) : zero4;         \
        } else {                                                                  \
            const float* Af0 = (const float*)Av + (size_t)(bm0 + rS) * 256 + (K0) + qS;       \
            const float* Af1 = (const float*)Av + (size_t)(bm0 + rS + 64) * 256 + (K0) + qS;  \
            pf00 = ok0 ? *(const float4*)(Af0)     : make_float4(0.f,0.f,0.f,0.f);\
            pf01 = ok0 ? *(const float4*)(Af0 + 4) : make_float4(0.f,0.f,0.f,0.f);\
            pf10 = ok1 ? *(const float4*)(Af1)     : make_float4(0.f,0.f,0.f,0.f);\
            pf11 = ok1 ? *(const float4*)(Af1 + 4) : make_float4(0.f,0.f,0.f,0.f);\
        }                                                                         \
        pb0 = *(const uint4*)(Bt + (size_t)(bn0 + rS) * 256 + (K0) + qS);         \
        pb1 = *(const uint4*)(Bt + (size_t)(bn0 + rS + 64) * 256 + (K0) + qS);    \
    } while (0)

    // ---- register tile -> smem (with fp32->bf16 convert in MODE 1) ----
    #define CVT4(dst, fa, fb)                                                     \
    do {                                                                          \
        __nv_bfloat162 c0 = __floats2bfloat162_rn((fa).x, (fa).y);                \
        __nv_bfloat162 c1 = __floats2bfloat162_rn((fa).z, (fa).w);                \
        __nv_bfloat162 c2 = __floats2bfloat162_rn((fb).x, (fb).y);                \
        __nv_bfloat162 c3 = __floats2bfloat162_rn((fb).z, (fb).w);                \
        dst = make_uint4(*(uint32_t*)&c0, *(uint32_t*)&c1,                        \
                         *(uint32_t*)&c2, *(uint32_t*)&c3);                       \
    } while (0)

    #define STORE_TILE()                                                          \
    do {                                                                          \
        uint4 sa0, sa1;                                                           \
        if (MODE == 0) { sa0 = pa0; sa1 = pa1; }                                  \
        else { CVT4(sa0, pf00, pf01); CVT4(sa1, pf10, pf11); }                    \
        *(uint4*)(&As[rS][qS])      = sa0;                                        \
        *(uint4*)(&As[rS + 64][qS]) = sa1;                                        \
        *(uint4*)(&Bs[rS][qS])      = pb0;                                        \
        *(uint4*)(&Bs[rS + 64][qS]) = pb1;                                        \
    } while (0)

    LOAD_TILE(0);

    for (int k0 = 0; k0 < 256; k0 += 32) {
        STORE_TILE();
        __syncthreads();
        if (k0 + 32 < 256) LOAD_TILE(k0 + 32);   // overlaps with MMA below

        #pragma unroll
        for (int sub = 0; sub < 2; sub++) {
            int ks = sub * 16 + t * 2;
            uint32_t a[4][4], b[4][2];
            #pragma unroll
            for (int mi = 0; mi < 4; mi++) {
                int r0 = wm * 64 + mi * 16 + g;
                a[mi][0] = *(const uint32_t*)(&As[r0][ks]);
                a[mi][1] = *(const uint32_t*)(&As[r0 + 8][ks]);
                a[mi][2] = *(const uint32_t*)(&As[r0][ks + 8]);
                a[mi][3] = *(const uint32_t*)(&As[r0 + 8][ks + 8]);
            }
            #pragma unroll
            for (int ni = 0; ni < 4; ni++) {
                int n0 = wn * 32 + ni * 8 + g;
                b[ni][0] = *(const uint32_t*)(&Bs[n0][ks]);
                b[ni][1] = *(const uint32_t*)(&Bs[n0][ks + 8]);
            }
            #pragma unroll
            for (int mi = 0; mi < 4; mi++)
                #pragma unroll
                for (int ni = 0; ni < 4; ni++)
                    asm volatile(
                        "mma.sync.aligned.m16n8k16.row.col.f32.bf16.bf16.f32 "
                        "{%0,%1,%2,%3}, {%4,%5,%6,%7}, {%8,%9}, {%0,%1,%2,%3};"
                        : "+f"(c[mi][ni][0]), "+f"(c[mi][ni][1]),
                          "+f"(c[mi][ni][2]), "+f"(c[mi][ni][3])
                        : "r"(a[mi][0]), "r"(a[mi][1]), "r"(a[mi][2]), "r"(a[mi][3]),
                          "r"(b[ni][0]), "r"(b[ni][1]));
        }
        __syncthreads();
    }

    // epilogue
    #pragma unroll
    for (int mi = 0; mi < 4; mi++) {
        int rbase = bm0 + wm * 64 + mi * 16 + g;
        #pragma unroll
        for (int ni = 0; ni < 4; ni++) {
            int cc = bn0 + wn * 32 + ni * 8 + t * 2;
            float b0 = bias[cc], b1v = bias[cc + 1];
            #pragma unroll
            for (int half = 0; half < 2; half++) {
                int rg = rbase + half * 8;
                if (rg >= M) continue;
                float lo = c[mi][ni][half * 2], hi = c[mi][ni][half * 2 + 1];
                if (MODE == 0) {
                    lo += b0; hi += b1v;
                    __nv_bfloat162 pv = __floats2bfloat162_rn(lo, hi);
                    *(uint32_t*)((__nv_bfloat16*)Cv + (size_t)rg * ldc + cc) =
                        *(uint32_t*)&pv;
                } else {
                    float dg = g_deg[rg];
                    lo = fmaxf(lo + dg * b0,  0.f) + x[(size_t)rg * EMBD + cc];
                    hi = fmaxf(hi + dg * b1v, 0.f) + x[(size_t)rg * EMBD + cc + 1];
                    *(float2*)((float*)Cv + (size_t)rg * ldc + cc) = make_float2(lo, hi);
                }
            }
        }
    }
    #undef LOAD_TILE
    #undef STORE_TILE
    #undef CVT4
}

// ------------- fused edge logits + exp + segment sum + degree ---------------
__global__ void edge_logexp(const int* __restrict__ ei,
                            const float* __restrict__ W2,
                            const float* __restrict__ b2)
{
    int e    = (blockIdx.x * blockDim.x + threadIdx.x) >> 5;
    int lane = threadIdx.x & 31;
    if (e >= ETOT) return;
    int s, d; edge_sd(e, ei, s, d);

    const uint4* pk = (const uint4*)(g_vppbf + (size_t)s * NCOMB + 256);
    const uint4* pq = (const uint4*)(g_vppbf + (size_t)d * NCOMB + 512);
    uint4 ku = pk[lane];
    uint4 qu = pq[lane];
    int j = lane & 15;                         // W2 block (cols mod 128)
    float4 w0 = ((const float4*)W2)[j * 2];
    float4 w1 = ((const float4*)W2)[j * 2 + 1];

    const __nv_bfloat162* kp = (const __nv_bfloat162*)&ku;
    const __nv_bfloat162* qp = (const __nv_bfloat162*)&qu;
    float2 k0 = __bfloat1622float2(kp[0]), q0 = __bfloat1622float2(qp[0]);
    float2 k1 = __bfloat1622float2(kp[1]), q1 = __bfloat1622float2(qp[1]);
    float2 k2 = __bfloat1622float2(kp[2]), q2 = __bfloat1622float2(qp[2]);
    float2 k3 = __bfloat1622float2(kp[3]), q3 = __bfloat1622float2(qp[3]);

    float p = fmaxf(k0.x + q0.x, 0.f) * w0.x + fmaxf(k0.y + q0.y, 0.f) * w0.y
            + fmaxf(k1.x + q1.x, 0.f) * w0.z + fmaxf(k1.y + q1.y, 0.f) * w0.w
            + fmaxf(k2.x + q2.x, 0.f) * w1.x + fmaxf(k2.y + q2.y, 0.f) * w1.y
            + fmaxf(k3.x + q3.x, 0.f) * w1.z + fmaxf(k3.y + q3.y, 0.f) * w1.w;

    #pragma unroll
    for (int o = 1; o <= 8; o <<= 1)
        p += __shfl_xor_sync(0xffffffffu, p, o);

    if ((lane & 15) == 0) {
        int h = lane >> 4;
        float ex = expf(p + b2[0]);
        g_a[(size_t)e * 2 + h] = ex;
        atomicAdd(&g_s[d * 2 + h], ex);
        if (lane == 0) atomicAdd(&g_deg[d], 1.0f);
    }
}

// --------------------- weighted scatter of v (warp per edge) ----------------
__global__ void edge_agg(const int* __restrict__ ei) {
    int e    = (blockIdx.x * blockDim.x + threadIdx.x) >> 5;
    int lane = threadIdx.x & 31;
    if (e >= ETOT) return;
    int s, d; edge_sd(e, ei, s, d);
    float al0 = g_a[(size_t)e * 2 + 0] / (g_s[d * 2 + 0] + 1e-16f);
    float al1 = g_a[(size_t)e * 2 + 1] / (g_s[d * 2 + 1] + 1e-16f);
    float al = (lane < 16) ? al0 : al1;        // lane covers cols 8*lane..8*lane+7

    uint4 vu = ((const uint4*)(g_vppbf + (size_t)s * NCOMB))[lane];
    const __nv_bfloat162* vp = (const __nv_bfloat162*)&vu;
    float2 v0 = __bfloat1622float2(vp[0]);
    float2 v1 = __bfloat1622float2(vp[1]);
    float2 v2 = __bfloat1622float2(vp[2]);
    float2 v3 = __bfloat1622float2(vp[3]);

    float* dst = g_agg + (size_t)d * EMBD + 8 * lane;
    asm volatile("red.global.add.v4.f32 [%0], {%1,%2,%3,%4};"
        :: "l"(dst), "f"(v0.x * al), "f"(v0.y * al), "f"(v1.x * al), "f"(v1.y * al)
        : "memory");
    asm volatile("red.global.add.v4.f32 [%0], {%1,%2,%3,%4};"
        :: "l"(dst + 4), "f"(v2.x * al), "f"(v2.y * al), "f"(v3.x * al), "f"(v3.y * al)
        : "memory");
}

// ----------------------------- launch ---------------------------------------
extern "C" void kernel_launch(void* const* d_in, const int* in_sizes, int n_in,
                              void* d_out, int out_size)
{
    const float* x    = (const float*)d_in[0];
    const int*   ei   = (const int*)d_in[1];
    const float* Wkqv = (const float*)d_in[2];
    const float* bkqv = (const float*)d_in[3];
    const float* W1   = (const float*)d_in[4];
    const float* b1   = (const float*)d_in[5];
    const float* W2   = (const float*)d_in[6];
    const float* b2   = (const float*)d_in[7];
    const float* Wout = (const float*)d_in[8];
    const float* bout = (const float*)d_in[9];
    float*       out  = (float*)d_out;

    float *bcomb, *agg;
    __nv_bfloat16 *xbf, *wcomb, *woutt, *vppbf;
    cudaGetSymbolAddress((void**)&vppbf, g_vppbf);
    cudaGetSymbolAddress((void**)&bcomb, g_bcomb);
    cudaGetSymbolAddress((void**)&xbf,   g_xbf);
    cudaGetSymbolAddress((void**)&wcomb, g_wcomb);
    cudaGetSymbolAddress((void**)&woutt, g_woutt);
    cudaGetSymbolAddress((void**)&agg,   g_agg);

    const int mtiles = (NN + 127) / 128;   // 391

    init_k<<<(NN * 64 + 255) / 256, 256>>>();
    conv_x<<<(NN * 64 + 255) / 256, 256>>>(x);
    prep_w<<<NCOMB, 256>>>(Wkqv, bkqv, W1, b1);
    prep_wout<<<256, 256>>>(Wout);

    // GEMM1: vppbf[N,768] = bf16(x_bf @ W_comb^T + b_comb)   (v | pk | pq)
    gemm_mma<0><<<dim3(NCOMB / 128, mtiles), 256>>>(
        xbf, wcomb, vppbf, NCOMB, bcomb, nullptr, NN);

    // fused edge logits+exp+segsum+deg, then weighted scatter
    edge_logexp<<<(ETOT + 7) / 8, 256>>>(ei, W2, b2);
    edge_agg<<<(ETOT + 7) / 8, 256>>>(ei);

    // GEMM2: out = relu(agg @ Wout^T + deg*bout) + x  (agg converted in-kernel)
    gemm_mma<1><<<dim3(EMBD / 128, mtiles), 256>>>(
        agg, woutt, out, EMBD, bout, x, NN);
}